// round 5
// baseline (speedup 1.0000x reference)
#include <cuda_runtime.h>
#include <cuda_bf16.h>

// ActionEncoder collapsed to a table lookup:
// out[b] = PRE[t][i0][i1] where PRE has only 2*64*64 = 8192 distinct float4s.
// Kernel 1 precomputes PRE (accurate tanhf); kernel 2 is a pure gather/stream.

#define MAX_N 64
#define NPRE (2 * MAX_N * MAX_N)   // 8192 entries, 128 KB

__device__ float4 PRE[NPRE];

__global__ __launch_bounds__(256)
void precompute_kernel(const float* __restrict__ W0, const float* __restrict__ b0,
                       const float* __restrict__ W1, const float* __restrict__ b1) {
    int e = blockIdx.x * blockDim.x + threadIdx.x;   // 0..8191
    if (e >= NPRE) return;
    int t  = e >> 12;
    int i0 = (e >> 6) & 63;
    int i1 = e & 63;

    float4 v;
    if (t == 0) {
        // slot-1 contributes nothing for t=0; slice replicated over i1
        v = make_float4(W0[0*64 + i0] + b0[0],
                        W0[1*64 + i0] + b0[1],
                        W0[2*64 + i0] + b0[2],
                        W0[3*64 + i0] + b0[3]);
    } else {
        v = make_float4(W1[0*128 + i0] + W1[0*128 + 64 + i1] + b1[0],
                        W1[1*128 + i0] + W1[1*128 + 64 + i1] + b1[1],
                        W1[2*128 + i0] + W1[2*128 + 64 + i1] + b1[2],
                        W1[3*128 + i0] + W1[3*128 + 64 + i1] + b1[3]);
    }
    PRE[e] = make_float4(tanhf(v.x), tanhf(v.y), tanhf(v.z), tanhf(v.w));
}

__global__ __launch_bounds__(256)
void gather_kernel(const int4* __restrict__ idx2,    // [B/2]: two (i0,i1) pairs
                   const int2* __restrict__ types2,  // [B/2]: two types
                   float4* __restrict__ out,         // [B]
                   int Bpairs) {
    int p = blockIdx.x * blockDim.x + threadIdx.x;
    if (p >= Bpairs) return;

    int4 ix = idx2[p];    // one coalesced 16B load covers both samples' indices
    int2 tt = types2[p];  // one coalesced  8B load covers both types

    int e0 = (tt.x << 12) | (ix.x << 6) | ix.y;
    int e1 = (tt.y << 12) | (ix.z << 6) | ix.w;

    // 128 KB table: L1-resident after warmup; gathers are L1 hits.
    float4 r0 = PRE[e0];
    float4 r1 = PRE[e1];

    out[2 * p]     = r0;
    out[2 * p + 1] = r1;
}

extern "C" void kernel_launch(void* const* d_in, const int* in_sizes, int n_in,
                              void* d_out, int out_size) {
    // metadata order: action_indecies, action_n_obj, action_types, W0, b0, W1, b1
    const int4*  idx2   = (const int4*) d_in[0];
    const int2*  types2 = (const int2*) d_in[2];
    const float* W0     = (const float*)d_in[3];
    const float* b0     = (const float*)d_in[4];
    const float* W1     = (const float*)d_in[5];
    const float* b1     = (const float*)d_in[6];
    float4* out = (float4*)d_out;

    int B = in_sizes[2];     // 524288 (even)
    int Bpairs = B >> 1;

    precompute_kernel<<<NPRE / 256, 256>>>(W0, b0, W1, b1);

    int threads = 256;
    int blocks  = (Bpairs + threads - 1) / threads;
    gather_kernel<<<blocks, threads>>>(idx2, types2, out, Bpairs);
}

// round 6
// speedup vs baseline: 1.0990x; 1.0990x over previous
#include <cuda_runtime.h>
#include <cuda_bf16.h>

// ActionEncoder: out[b] = tanh(b_t + sum_s W_t[:, s*64 + idx[b,s]])
// Branchless unified smem tables (t*64+i; Tb zero-padded for t=0).
// ITEMS=4 adjacent samples/thread: types as int4, idx as 2x int4 (coalesced).
// tanh via Pade(7,6) rational on FMA pipe (1 MUFU.RCP) instead of 2x MUFU.

#define MAX_N 64

__device__ __forceinline__ float ftanh(float x) {
    // Pade(7,6): exact to <1e-7 for |x|<=1 (preacts are ~0.09 RMS; |x|>1 is ~1e-31).
    float x2 = x * x;
    float n = ((x2 + 378.f) * x2 + 17325.f) * x2 + 135135.f;
    float d = ((28.f * x2 + 3150.f) * x2 + 62370.f) * x2 + 135135.f;
    return __fdividef(x * n, d);
}

__device__ __forceinline__ float4 enc(const float4* Ta, const float4* Tb,
                                      int t, int i0, int i1) {
    int off = t << 6;
    float4 a = Ta[off + i0];
    float4 c = Tb[off + i1];
    return make_float4(ftanh(a.x + c.x), ftanh(a.y + c.y),
                       ftanh(a.z + c.z), ftanh(a.w + c.w));
}

__global__ __launch_bounds__(256)
void action_encoder_kernel(const int4* __restrict__ idx2,    // [B/2] two (i0,i1) pairs each
                           const int4* __restrict__ types4,  // [B/4] four types each
                           const float* __restrict__ W0,     // [4,64]
                           const float* __restrict__ b0,     // [4]
                           const float* __restrict__ W1,     // [4,128]
                           const float* __restrict__ b1,     // [4]
                           float4* __restrict__ out,         // [B]
                           int Bquads) {
    __shared__ float4 Ta[2 * MAX_N];  // slot-0 contribution, bias folded
    __shared__ float4 Tb[2 * MAX_N];  // slot-1 contribution, zero for t=0
    int tid = threadIdx.x;
    if (tid < MAX_N) {
        Ta[tid] = make_float4(W0[0*64 + tid] + b0[0],
                              W0[1*64 + tid] + b0[1],
                              W0[2*64 + tid] + b0[2],
                              W0[3*64 + tid] + b0[3]);
        Tb[tid] = make_float4(0.f, 0.f, 0.f, 0.f);
    } else if (tid < 2 * MAX_N) {
        int j = tid - MAX_N;
        Ta[tid] = make_float4(W1[0*128 + j] + b1[0],
                              W1[1*128 + j] + b1[1],
                              W1[2*128 + j] + b1[2],
                              W1[3*128 + j] + b1[3]);
        Tb[tid] = make_float4(W1[0*128 + 64 + j],
                              W1[1*128 + 64 + j],
                              W1[2*128 + 64 + j],
                              W1[3*128 + 64 + j]);
    }
    __syncthreads();

    int q = blockIdx.x * blockDim.x + tid;   // quad index (4 samples)
    if (q >= Bquads) return;

    // Front-batched, fully coalesced loads: 2x int4 idx + 1x int4 types.
    int4 ixA = idx2[2 * q];        // samples 0,1: (i0,i1,i0,i1)
    int4 ixB = idx2[2 * q + 1];    // samples 2,3
    int4 tt  = types4[q];          // 4 types

    float4 r0 = enc(Ta, Tb, tt.x, ixA.x, ixA.y);
    float4 r1 = enc(Ta, Tb, tt.y, ixA.z, ixA.w);
    float4 r2 = enc(Ta, Tb, tt.z, ixB.x, ixB.y);
    float4 r3 = enc(Ta, Tb, tt.w, ixB.z, ixB.w);

    out[4 * q]     = r0;
    out[4 * q + 1] = r1;
    out[4 * q + 2] = r2;
    out[4 * q + 3] = r3;
}

extern "C" void kernel_launch(void* const* d_in, const int* in_sizes, int n_in,
                              void* d_out, int out_size) {
    // metadata order: action_indecies, action_n_obj, action_types, W0, b0, W1, b1
    const int4*  idx2   = (const int4*) d_in[0];
    const int4*  types4 = (const int4*) d_in[2];
    const float* W0     = (const float*)d_in[3];
    const float* b0     = (const float*)d_in[4];
    const float* W1     = (const float*)d_in[5];
    const float* b1     = (const float*)d_in[6];
    float4* out = (float4*)d_out;

    int B = in_sizes[2];      // 524288 (divisible by 4)
    int Bquads = B >> 2;      // 131072

    int threads = 256;
    int blocks  = (Bquads + threads - 1) / threads;  // 512
    action_encoder_kernel<<<blocks, threads>>>(idx2, types4, W0, b0, W1, b1,
                                               out, Bquads);
}

// round 7
// speedup vs baseline: 1.3333x; 1.2132x over previous
#include <cuda_runtime.h>
#include <cuda_bf16.h>

// ActionEncoder: out[b] = tanh(b_t + sum_s W_t[:, s*64 + idx[b,s]])
// Single-wave persistent kernel: grid = 4 CTAs/SM * 148 SMs, grid-stride loop.
// smem table build paid once per resident CTA; no wave transitions.
// Branchless unified tables (t*64+i; Tb zero-padded for t=0), __expf tanh.

#define MAX_N 64
#define SMS 148
#define BLOCKS_PER_SM 4
#define THREADS 256

__device__ __forceinline__ float ftanh(float x) {
    // tanh(x) = (e^{2x}-1)/(e^{2x}+1); branch-free, MUFU-backed.
    float e = __expf(2.0f * x);
    return __fdividef(e - 1.0f, e + 1.0f);
}

__device__ __forceinline__ float4 enc(const float4* Ta, const float4* Tb,
                                      int t, int i0, int i1) {
    int off = t << 6;
    float4 a = Ta[off + i0];
    float4 c = Tb[off + i1];
    return make_float4(ftanh(a.x + c.x), ftanh(a.y + c.y),
                       ftanh(a.z + c.z), ftanh(a.w + c.w));
}

__global__ __launch_bounds__(THREADS, BLOCKS_PER_SM)
void action_encoder_kernel(const int4* __restrict__ idx2,    // [B/2] two (i0,i1) pairs
                           const int2* __restrict__ types2,  // [B/2] two types
                           const float* __restrict__ W0,     // [4,64]
                           const float* __restrict__ b0,     // [4]
                           const float* __restrict__ W1,     // [4,128]
                           const float* __restrict__ b1,     // [4]
                           float4* __restrict__ out,         // [B]
                           int Bpairs) {
    __shared__ float4 Ta[2 * MAX_N];  // slot-0 contribution, bias folded
    __shared__ float4 Tb[2 * MAX_N];  // slot-1 contribution, zero for t=0
    int tid = threadIdx.x;
    if (tid < MAX_N) {
        Ta[tid] = make_float4(W0[0*64 + tid] + b0[0],
                              W0[1*64 + tid] + b0[1],
                              W0[2*64 + tid] + b0[2],
                              W0[3*64 + tid] + b0[3]);
        Tb[tid] = make_float4(0.f, 0.f, 0.f, 0.f);
    } else if (tid < 2 * MAX_N) {
        int j = tid - MAX_N;
        Ta[tid] = make_float4(W1[0*128 + j] + b1[0],
                              W1[1*128 + j] + b1[1],
                              W1[2*128 + j] + b1[2],
                              W1[3*128 + j] + b1[3]);
        Tb[tid] = make_float4(W1[0*128 + 64 + j],
                              W1[1*128 + 64 + j],
                              W1[2*128 + 64 + j],
                              W1[3*128 + 64 + j]);
    }
    __syncthreads();

    int stride = gridDim.x * blockDim.x;
    // Grid-stride over pairs; each iteration: 1x int4 + 1x int2 coalesced loads,
    // 4 LDS.128, 8 tanh, 2 coalesced STG.128.
    for (int p = blockIdx.x * blockDim.x + tid; p < Bpairs; p += stride) {
        int4 ix = idx2[p];
        int2 tt = types2[p];
        float4 r0 = enc(Ta, Tb, tt.x, ix.x, ix.y);
        float4 r1 = enc(Ta, Tb, tt.y, ix.z, ix.w);
        out[2 * p]     = r0;
        out[2 * p + 1] = r1;
    }
}

extern "C" void kernel_launch(void* const* d_in, const int* in_sizes, int n_in,
                              void* d_out, int out_size) {
    // metadata order: action_indecies, action_n_obj, action_types, W0, b0, W1, b1
    const int4*  idx2   = (const int4*) d_in[0];
    const int2*  types2 = (const int2*) d_in[2];
    const float* W0     = (const float*)d_in[3];
    const float* b0     = (const float*)d_in[4];
    const float* W1     = (const float*)d_in[5];
    const float* b1     = (const float*)d_in[6];
    float4* out = (float4*)d_out;

    int B = in_sizes[2];      // 524288 (even)
    int Bpairs = B >> 1;      // 262144

    int blocks = SMS * BLOCKS_PER_SM;  // 592: exactly one resident wave
    action_encoder_kernel<<<blocks, THREADS>>>(idx2, types2, W0, b0, W1, b1,
                                               out, Bpairs);
}